// round 12
// baseline (speedup 1.0000x reference)
#include <cuda_runtime.h>
#include <cstddef>

// Problem constants
#define NN    16
#define DIM   32
#define FEAT  192
#define KTOT  (DIM*FEAT)      // 6144
#define YSZ   (NN*DIM*FEAT)   // 98304

// Einsum tiling
#define CPC    4               // c's per CTA (A folded into W scalar)
#define NCG    (FEAT/CPC)      // 48 c-groups
#define KSPLIT 12
#define KCTA   (KTOT/KSPLIT)   // 512
#define NST    (KCTA/32)       // 16 stages of 32 k's
#define KSTRIDE ((size_t)32 * FEAT * DIM)   // W float-stride of one 32-k stage
#define WBUFB  16384            // bytes per W ring buffer (32k*4c*32m*4B)

// Scratch (no allocations allowed -> device globals)
__device__ float g_ybuf[YSZ];
__device__ float g_h1[YSZ];
__device__ float g_h2[YSZ];

__device__ __forceinline__ void cp16(unsigned dst, const void* src) {
    asm volatile("cp.async.cg.shared.global [%0], [%1], 16;\n" :: "r"(dst), "l"(src));
}
#define CP_COMMIT() asm volatile("cp.async.commit_group;\n" ::: "memory")
#define CP_WAIT1()  asm volatile("cp.async.wait_group 1;\n" ::: "memory")

// ---------------------------------------------------------------------------
// Fused weighted einsum, ring-3 cp.async W pipeline, ONE barrier per stage:
//   Y[n, m, c] += sum_k H0[n,k] * A0[k%192, c] * W[k, c, m]   (+ H1/A1 stream)
// W viewed as [KTOT][FEAT][DIM]. Per 32-k stage the CTA stages the 16KB tile
// W[32k][4c][32m] via cp.async into a 3-deep ring (dynamic smem) and the 2KB
// h tile via a register pipeline one stage ahead. Warp w computes
// kk = w*8..w*8+7, all 16 n, all 4 c.
// Single stage-top barrier proves both hazards safe:
//  - h buffer (s+1)&1 written at end of stage s == buffer read in stage s-1,
//    whose readers all passed the stage-s barrier first;
//  - W ring slot (wb+2)%3 written at stage s == slot read in stage s-1, same.
// cp.async groups: prologue G0(st0) G1(st1); iter s commits G(s+2)(st s+2);
// at stage t's wait_group 1, groups 0..t are complete -> W[t] ready.
// ---------------------------------------------------------------------------
template<bool TWO_H, int MINB>
__global__ void __launch_bounds__(128, MINB)
einsum_kernel(const float* __restrict__ W,
              const float* __restrict__ H0, const float* __restrict__ A0,
              const float* __restrict__ H1, const float* __restrict__ A1,
              float* __restrict__ Y)
{
    extern __shared__ __align__(16) float dynsm[];     // 3 * 4096 floats
    const int ks   = blockIdx.x;           // 0..KSPLIT-1
    const int c0   = blockIdx.y * CPC;     // 0..191 step 4
    const int tid  = threadIdx.x;
    const int w    = tid >> 5;
    const int lane = tid & 31;

    __shared__ __align__(16) float2 shh [2][32][8];     // h stream0, 4KB
    __shared__ __align__(16) float2 shh2[TWO_H ? 2*32*8 : 8];
    __shared__ float sh_a0[CPC][FEAT];
    __shared__ float sh_a1[TWO_H ? CPC * FEAT : 1];

    // Stage A columns for this CTA's 4 c's (visible after stage-0 barrier).
    for (int i = tid; i < CPC * FEAT; i += 128) {
        const int cc = i / FEAT, f = i - cc * FEAT;
        sh_a0[cc][f] = A0[f * FEAT + c0 + cc];
        if (TWO_H) sh_a1[cc * FEAT + f] = A1[f * FEAT + c0 + cc];
    }

    const int kbase = ks * KCTA;
    const int kk_h  = tid >> 2;            // 0..31 : k-row this thread stages
    const int q     = tid & 3;             // n-quad

    // ---- running pointers ----
    const float* wsrc = W + ((size_t)(kbase + (tid >> 5)) * FEAT + c0) * DIM
                          + (tid & 31) * 4;
    const unsigned wdstb = (unsigned)__cvta_generic_to_shared(
        dynsm + (tid >> 5) * 128 + (tid & 31) * 4);
    const float* hsrc0 = H0 + kbase + kk_h;
    const float* hsrc1 = TWO_H ? (H1 + kbase + kk_h) : nullptr;

    auto copy_w = [&](unsigned dst, const float* src) {
#pragma unroll
        for (int j = 0; j < 8; ++j)
            cp16(dst + j * 4 * 512,
                 src + (size_t)j * 4 * FEAT * DIM);
    };

    float hv[4], hv2[4];
    auto load_h = [&](int soff) {
        const float* hp = hsrc0 + soff * 32;
#pragma unroll
        for (int j = 0; j < 4; ++j) hv[j] = hp[(4 * q + j) * KTOT];
        if (TWO_H) {
            const float* hq = hsrc1 + soff * 32;
#pragma unroll
            for (int j = 0; j < 4; ++j) hv2[j] = hq[(4 * q + j) * KTOT];
        }
    };
    auto store_h = [&](int buf) {
        *reinterpret_cast<float4*>(&shh[buf][kk_h][2 * q]) =
            make_float4(hv[0], hv[1], hv[2], hv[3]);
        if (TWO_H)
            *reinterpret_cast<float4*>(&shh2[(buf * 32 + kk_h) * 8 + 2 * q]) =
                make_float4(hv2[0], hv2[1], hv2[2], hv2[3]);
    };

    unsigned long long acc[CPC][8];
#pragma unroll
    for (int cc = 0; cc < CPC; ++cc)
#pragma unroll
        for (int p = 0; p < 8; ++p) acc[cc][p] = 0ull;

    // ---- pipeline prologue: copies for stages 0,1 in flight, h[0] staged ----
    copy_w(wdstb,         wsrc);            CP_COMMIT();
    copy_w(wdstb + WBUFB, wsrc + KSTRIDE);  CP_COMMIT();
    wsrc += 2 * KSTRIDE;                    // next copy target = stage 2
    load_h(0);
    store_h(0);

    const int kk0 = w * 8;
    int fb = kbase % FEAT;
    int wb = 0;                             // ring slot of stage s

    for (int s = 0; s < NST; ++s) {
        if (s + 1 < NST) load_h(s + 1);      // LDG issue, overlaps wait

        CP_WAIT1();                          // copy[s] complete (in-order)
        __syncthreads();                     // W[s]+h[s] visible; slot freed

        if (s + 2 < NST) {
            const int cb = (wb >= 1) ? wb - 1 : 2;   // (wb+2)%3
            copy_w(wdstb + cb * WBUFB, wsrc);
            wsrc += KSTRIDE;
        }
        CP_COMMIT();                         // (possibly empty) keeps counts

        const int   buf  = s & 1;
        const float* wcur = dynsm + wb * 4096;

#pragma unroll
        for (int i = 0; i < 8; ++i) {
            const int kk = kk0 + i;
            const float* wrow = wcur + kk * 128 + lane;
            const float wr0 = wrow[0],  wr1 = wrow[32],
                        wr2 = wrow[64], wr3 = wrow[96];
            const float wr[4] = {wr0, wr1, wr2, wr3};
            const ulonglong2* hr =
                reinterpret_cast<const ulonglong2*>(&shh[buf][kk][0]);
            const ulonglong2 h0 = hr[0], h1 = hr[1], h2 = hr[2], h3 = hr[3];
            ulonglong2 g0, g1, g2, g3;
            if (TWO_H) {
                const ulonglong2* gr = reinterpret_cast<const ulonglong2*>(
                    &shh2[(buf * 32 + kk) * 8]);
                g0 = gr[0]; g1 = gr[1]; g2 = gr[2]; g3 = gr[3];
            }
#pragma unroll
            for (int cc = 0; cc < CPC; ++cc) {
                {
                    const float wv = wr[cc] * sh_a0[cc][fb + kk];
                    unsigned long long wd;
                    asm("mov.b64 %0, {%1, %1};" : "=l"(wd) : "f"(wv));
                    asm("fma.rn.f32x2 %0, %1, %2, %0;" : "+l"(acc[cc][0]) : "l"(h0.x), "l"(wd));
                    asm("fma.rn.f32x2 %0, %1, %2, %0;" : "+l"(acc[cc][1]) : "l"(h0.y), "l"(wd));
                    asm("fma.rn.f32x2 %0, %1, %2, %0;" : "+l"(acc[cc][2]) : "l"(h1.x), "l"(wd));
                    asm("fma.rn.f32x2 %0, %1, %2, %0;" : "+l"(acc[cc][3]) : "l"(h1.y), "l"(wd));
                    asm("fma.rn.f32x2 %0, %1, %2, %0;" : "+l"(acc[cc][4]) : "l"(h2.x), "l"(wd));
                    asm("fma.rn.f32x2 %0, %1, %2, %0;" : "+l"(acc[cc][5]) : "l"(h2.y), "l"(wd));
                    asm("fma.rn.f32x2 %0, %1, %2, %0;" : "+l"(acc[cc][6]) : "l"(h3.x), "l"(wd));
                    asm("fma.rn.f32x2 %0, %1, %2, %0;" : "+l"(acc[cc][7]) : "l"(h3.y), "l"(wd));
                }
                if (TWO_H) {
                    const float wv1 = wr[cc] * sh_a1[cc * FEAT + fb + kk];
                    unsigned long long wd1;
                    asm("mov.b64 %0, {%1, %1};" : "=l"(wd1) : "f"(wv1));
                    asm("fma.rn.f32x2 %0, %1, %2, %0;" : "+l"(acc[cc][0]) : "l"(g0.x), "l"(wd1));
                    asm("fma.rn.f32x2 %0, %1, %2, %0;" : "+l"(acc[cc][1]) : "l"(g0.y), "l"(wd1));
                    asm("fma.rn.f32x2 %0, %1, %2, %0;" : "+l"(acc[cc][2]) : "l"(g1.x), "l"(wd1));
                    asm("fma.rn.f32x2 %0, %1, %2, %0;" : "+l"(acc[cc][3]) : "l"(g1.y), "l"(wd1));
                    asm("fma.rn.f32x2 %0, %1, %2, %0;" : "+l"(acc[cc][4]) : "l"(g2.x), "l"(wd1));
                    asm("fma.rn.f32x2 %0, %1, %2, %0;" : "+l"(acc[cc][5]) : "l"(g2.y), "l"(wd1));
                    asm("fma.rn.f32x2 %0, %1, %2, %0;" : "+l"(acc[cc][6]) : "l"(g3.x), "l"(wd1));
                    asm("fma.rn.f32x2 %0, %1, %2, %0;" : "+l"(acc[cc][7]) : "l"(g3.y), "l"(wd1));
                }
            }
        }

        if (s + 1 < NST) store_h((s + 1) & 1);

        wb = (wb + 1 == 3) ? 0 : wb + 1;
        fb += 32; if (fb == FEAT) fb = 0;
    }

    // ---- cross-warp reduction (W ring reused), then atomics ----
    __syncthreads();
    unsigned long long* sred = reinterpret_cast<unsigned long long*>(dynsm);
#pragma unroll
    for (int cc = 0; cc < CPC; ++cc)
#pragma unroll
        for (int p = 0; p < 8; ++p)
            sred[w * 1024 + cc * 256 + p * 32 + lane] = acc[cc][p];
    __syncthreads();

#pragma unroll
    for (int r = 0; r < 8; ++r) {
        const int idx = tid + r * 128;     // (cc, p, m)
        const unsigned long long v0 = sred[idx];
        const unsigned long long v1 = sred[idx + 1024];
        const unsigned long long v2 = sred[idx + 2048];
        const unsigned long long v3 = sred[idx + 3072];
        unsigned long long s01, s23, sm;
        asm("add.rn.f32x2 %0, %1, %2;" : "=l"(s01) : "l"(v0), "l"(v1));
        asm("add.rn.f32x2 %0, %1, %2;" : "=l"(s23) : "l"(v2), "l"(v3));
        asm("add.rn.f32x2 %0, %1, %2;" : "=l"(sm)  : "l"(s01), "l"(s23));
        float lo, hi;
        asm("mov.b64 {%0, %1}, %2;" : "=f"(lo), "=f"(hi) : "l"(sm));
        const int cc = idx >> 8, p = (idx >> 5) & 7, m = idx & 31;
        float* yp = Y + ((size_t)(2 * p) * DIM + m) * FEAT + c0 + cc;
        atomicAdd(yp,                      lo);
        atomicAdd(yp + (size_t)DIM * FEAT, hi);
    }
}

// ---------------------------------------------------------------------------
// Fused LayerNorm (+ optional next-layer transition matmul).
// LN over (m,c) per n (6144 elems), eps=1e-5, no affine; scale-invariance
// lets us skip the mean-over-terms division. If Hmm != nullptr, AFTER all LN
// reads the block overwrites its ybuf slice with (Hmm @ M) — the initializer
// of the next layer's accumulation (einsum atomicAdds on top).
// ---------------------------------------------------------------------------
__global__ void __launch_bounds__(384)
ln_mm_kernel(float* __restrict__ Y, float* __restrict__ O,
             const float* __restrict__ Hmm, const float* __restrict__ M)
{
    const int n = blockIdx.x;
    const int t = threadIdx.x;
    const float* y = Y + (size_t)n * KTOT;

    __shared__ float xs[32 * FEAT];        // mm input rows, 24KB
    __shared__ float ss[12], qs[12];
    __shared__ float mean_b, rstd_b;

    if (Hmm) {
        const float* hp = Hmm + (size_t)n * KTOT;
        for (int i = t; i < KTOT; i += 384) xs[i] = hp[i];
    }

    float vals[16];
    float s = 0.f, q = 0.f;
#pragma unroll
    for (int r = 0; r < 16; ++r) {
        const float v = y[t + r * 384];
        vals[r] = v;
        s += v;
        q = fmaf(v, v, q);
    }
#pragma unroll
    for (int o = 16; o > 0; o >>= 1) {
        s += __shfl_xor_sync(0xffffffffu, s, o);
        q += __shfl_xor_sync(0xffffffffu, q, o);
    }
    const int wid = t >> 5, ln = t & 31;
    if (ln == 0) { ss[wid] = s; qs[wid] = q; }
    __syncthreads();
    if (t == 0) {
        float S = 0.f, Q = 0.f;
#pragma unroll
        for (int i = 0; i < 12; ++i) { S += ss[i]; Q += qs[i]; }
        const float mean = S * (1.0f / KTOT);
        const float var  = Q * (1.0f / KTOT) - mean * mean;
        mean_b = mean;
        rstd_b = rsqrtf(var + 1e-5f);
    }
    __syncthreads();
    const float mean = mean_b, rstd = rstd_b;
#pragma unroll
    for (int r = 0; r < 16; ++r)
        O[(size_t)n * KTOT + t + r * 384] = (vals[r] - mean) * rstd;

    if (Hmm) {
        // All LN reads of Y finished (barrier above) -> safe to overwrite.
        const int c    = (t < FEAT) ? t : t - FEAT;
        const int half = (t < FEAT) ? 0 : 1;
        float a[16];
#pragma unroll
        for (int r = 0; r < 16; ++r) a[r] = 0.f;
        const float* Mc = M + c;
        const float* xb = xs + half * 16 * FEAT;
#pragma unroll 2
        for (int f = 0; f < FEAT; ++f) {
            const float mv = Mc[f * FEAT];
            const float* xr = xb + f;
#pragma unroll
            for (int r = 0; r < 16; ++r)
                a[r] = fmaf(xr[r * FEAT], mv, a[r]);
        }
        float* yo = Y + (size_t)n * KTOT + half * 16 * FEAT + c;
#pragma unroll
        for (int r = 0; r < 16; ++r) yo[r * FEAT] = a[r];
    }
}

// ---------------------------------------------------------------------------
extern "C" void kernel_launch(void* const* d_in, const int* in_sizes, int n_in,
                              void* d_out, int out_size)
{
    const float* x   = (const float*)d_in[0];
    const float* s2t = (const float*)d_in[1];
    const float* t2s = (const float*)d_in[2];
    const float* s0  = (const float*)d_in[3];
    const float* s1  = (const float*)d_in[4];
    // d_in[5] = s2 : unused by the 4-layer schedule
    const float* t0  = (const float*)d_in[6];
    const float* t1  = (const float*)d_in[7];
    const float* t2  = (const float*)d_in[8];
    float* out = (float*)d_out;

    float *ybuf, *h1, *h2;
    cudaGetSymbolAddress((void**)&ybuf, g_ybuf);
    cudaGetSymbolAddress((void**)&h1,   g_h1);
    cudaGetSymbolAddress((void**)&h2,   g_h2);

    const dim3 eg(KSPLIT, NCG);            // 12 x 48 = 576 CTAs
    const int  wsm = 3 * WBUFB;            // 48KB dynamic W ring

    // Opt-in for 48KB dynamic + static smem (host-side config, not a stream
    // op -> legal under graph capture). Idempotent, cheap.
    cudaFuncSetAttribute((const void*)einsum_kernel<false, 4>,
                         cudaFuncAttributeMaxDynamicSharedMemorySize, wsm);
    cudaFuncSetAttribute((const void*)einsum_kernel<true, 3>,
                         cudaFuncAttributeMaxDynamicSharedMemorySize, wsm);

    // Layer 1: y1 = einsum(x, s2t, t0) -> LN -> h1 ; ybuf := x@s1 (layer-2 init)
    cudaMemsetAsync(ybuf, 0, YSZ * sizeof(float));
    einsum_kernel<false, 4><<<eg, 128, wsm>>>(s2t, x, t0, nullptr, nullptr, ybuf);
    ln_mm_kernel<<<NN, 384>>>(ybuf, h1, x, s1);

    // Layer 2: y2 = x@s1 + einsum(h1, t2s, s0) -> LN -> h2 ; ybuf := h1@t1
    einsum_kernel<false, 4><<<eg, 128, wsm>>>(t2s, h1, s0, nullptr, nullptr, ybuf);
    ln_mm_kernel<<<NN, 384>>>(ybuf, h2, h1, t1);

    // Layer 3: y3 = h1@t1 + einsum(x, s2t, t2) + einsum(h2, s2t, t0) -> LN -> out
    einsum_kernel<true, 3><<<eg, 128, wsm>>>(s2t, x, t2, h2, t0, ybuf);
    ln_mm_kernel<<<NN, 384>>>(ybuf, out, nullptr, nullptr);
}

// round 13
// speedup vs baseline: 1.4210x; 1.4210x over previous
#include <cuda_runtime.h>
#include <cstddef>

// Problem constants
#define NN    16
#define DIM   32
#define FEAT  192
#define KTOT  (DIM*FEAT)      // 6144
#define YSZ   (NN*DIM*FEAT)   // 98304

// Einsum tiling
#define CPC    4               // c's per CTA (A folded into W scalar)
#define NCG    (FEAT/CPC)      // 48 c-groups
#define KSPLIT 12
#define KCTA   (KTOT/KSPLIT)   // 512
#define NST    (KCTA/32)       // 16 stages of 32 k's
#define KSTRIDE ((size_t)32 * FEAT * DIM)   // W float-stride of one 32-k stage
#define WBUFB  16384            // bytes per W ring buffer (32k*4c*32m*4B)

// Scratch (no allocations allowed -> device globals)
__device__ float g_ybuf[YSZ];
__device__ float g_h1[YSZ];
__device__ float g_h2[YSZ];

__device__ __forceinline__ void cp16(unsigned dst, const void* src) {
    asm volatile("cp.async.cg.shared.global [%0], [%1], 16;\n" :: "r"(dst), "l"(src));
}
#define CP_COMMIT() asm volatile("cp.async.commit_group;\n" ::: "memory")
#define CP_WAIT1()  asm volatile("cp.async.wait_group 1;\n" ::: "memory")

// ---------------------------------------------------------------------------
// Fused weighted einsum, ring-3 cp.async W pipeline, ONE barrier per stage:
//   Y[n, m, c] += sum_k H0[n,k] * A0[k%192, c] * W[k, c, m]   (+ H1/A1 stream)
// W viewed as [KTOT][FEAT][DIM]. Per 32-k stage the CTA stages the 16KB tile
// W[32k][4c][32m] via cp.async into a 3-deep ring (dynamic smem) and the 2KB
// h tile via a register pipeline one stage ahead. Warp w computes
// kk = w*8..w*8+7, all 16 n, all 4 c.
// ---------------------------------------------------------------------------
template<bool TWO_H, int MINB>
__global__ void __launch_bounds__(128, MINB)
einsum_kernel(const float* __restrict__ W,
              const float* __restrict__ H0, const float* __restrict__ A0,
              const float* __restrict__ H1, const float* __restrict__ A1,
              float* __restrict__ Y)
{
    extern __shared__ __align__(16) float dynsm[];     // 3 * 4096 floats
    const int ks   = blockIdx.x;           // 0..KSPLIT-1
    const int c0   = blockIdx.y * CPC;     // 0..191 step 4
    const int tid  = threadIdx.x;
    const int w    = tid >> 5;
    const int lane = tid & 31;

    __shared__ __align__(16) float2 shh [2][32][8];     // h stream0, 4KB
    __shared__ __align__(16) float2 shh2[TWO_H ? 2*32*8 : 8];
    __shared__ float sh_a0[CPC][FEAT];
    __shared__ float sh_a1[TWO_H ? CPC * FEAT : 1];

    // Stage A columns for this CTA's 4 c's (visible after stage-0 barrier).
    for (int i = tid; i < CPC * FEAT; i += 128) {
        const int cc = i / FEAT, f = i - cc * FEAT;
        sh_a0[cc][f] = A0[f * FEAT + c0 + cc];
        if (TWO_H) sh_a1[cc * FEAT + f] = A1[f * FEAT + c0 + cc];
    }

    const int kbase = ks * KCTA;
    const int kk_h  = tid >> 2;            // 0..31 : k-row this thread stages
    const int q     = tid & 3;             // n-quad

    // ---- running pointers ----
    const float* wsrc = W + ((size_t)(kbase + (tid >> 5)) * FEAT + c0) * DIM
                          + (tid & 31) * 4;
    const unsigned wdstb = (unsigned)__cvta_generic_to_shared(
        dynsm + (tid >> 5) * 128 + (tid & 31) * 4);
    const float* hsrc0 = H0 + kbase + kk_h;
    const float* hsrc1 = TWO_H ? (H1 + kbase + kk_h) : nullptr;

    auto copy_w = [&](unsigned dst, const float* src) {
#pragma unroll
        for (int j = 0; j < 8; ++j)
            cp16(dst + j * 4 * 512,
                 src + (size_t)j * 4 * FEAT * DIM);
    };

    float hv[4], hv2[4];
    auto load_h = [&](int soff) {
        const float* hp = hsrc0 + soff * 32;
#pragma unroll
        for (int j = 0; j < 4; ++j) hv[j] = hp[(4 * q + j) * KTOT];
        if (TWO_H) {
            const float* hq = hsrc1 + soff * 32;
#pragma unroll
            for (int j = 0; j < 4; ++j) hv2[j] = hq[(4 * q + j) * KTOT];
        }
    };
    auto store_h = [&](int buf) {
        *reinterpret_cast<float4*>(&shh[buf][kk_h][2 * q]) =
            make_float4(hv[0], hv[1], hv[2], hv[3]);
        if (TWO_H)
            *reinterpret_cast<float4*>(&shh2[(buf * 32 + kk_h) * 8 + 2 * q]) =
                make_float4(hv2[0], hv2[1], hv2[2], hv2[3]);
    };

    unsigned long long acc[CPC][8];
#pragma unroll
    for (int cc = 0; cc < CPC; ++cc)
#pragma unroll
        for (int p = 0; p < 8; ++p) acc[cc][p] = 0ull;

    // ---- pipeline prologue: copies for stages 0,1 in flight, h[0] staged ----
    copy_w(wdstb,         wsrc);            CP_COMMIT();
    copy_w(wdstb + WBUFB, wsrc + KSTRIDE);  CP_COMMIT();
    wsrc += 2 * KSTRIDE;                    // next copy target = stage 2
    load_h(0);
    store_h(0);

    const int kk0 = w * 8;
    int fb = kbase % FEAT;
    int wb = 0;                             // ring slot of stage s

    for (int s = 0; s < NST; ++s) {
        if (s + 1 < NST) load_h(s + 1);      // LDG issue, overlaps wait

        CP_WAIT1();                          // copy[s] complete (in-order)
        __syncthreads();                     // W[s]+h[s] visible; slot freed

        if (s + 2 < NST) {
            const int cb = (wb >= 1) ? wb - 1 : 2;   // (wb+2)%3
            copy_w(wdstb + cb * WBUFB, wsrc);
            wsrc += KSTRIDE;
        }
        CP_COMMIT();                         // (possibly empty) keeps counts

        const int   buf  = s & 1;
        const float* wcur = dynsm + wb * 4096;

#pragma unroll
        for (int i = 0; i < 8; ++i) {
            const int kk = kk0 + i;
            const float* wrow = wcur + kk * 128 + lane;
            const float wr0 = wrow[0],  wr1 = wrow[32],
                        wr2 = wrow[64], wr3 = wrow[96];
            const float wr[4] = {wr0, wr1, wr2, wr3};
            const ulonglong2* hr =
                reinterpret_cast<const ulonglong2*>(&shh[buf][kk][0]);
            const ulonglong2 h0 = hr[0], h1 = hr[1], h2 = hr[2], h3 = hr[3];
            ulonglong2 g0, g1, g2, g3;
            if (TWO_H) {
                const ulonglong2* gr = reinterpret_cast<const ulonglong2*>(
                    &shh2[(buf * 32 + kk) * 8]);
                g0 = gr[0]; g1 = gr[1]; g2 = gr[2]; g3 = gr[3];
            }
#pragma unroll
            for (int cc = 0; cc < CPC; ++cc) {
                {
                    const float wv = wr[cc] * sh_a0[cc][fb + kk];
                    unsigned long long wd;
                    asm("mov.b64 %0, {%1, %1};" : "=l"(wd) : "f"(wv));
                    asm("fma.rn.f32x2 %0, %1, %2, %0;" : "+l"(acc[cc][0]) : "l"(h0.x), "l"(wd));
                    asm("fma.rn.f32x2 %0, %1, %2, %0;" : "+l"(acc[cc][1]) : "l"(h0.y), "l"(wd));
                    asm("fma.rn.f32x2 %0, %1, %2, %0;" : "+l"(acc[cc][2]) : "l"(h1.x), "l"(wd));
                    asm("fma.rn.f32x2 %0, %1, %2, %0;" : "+l"(acc[cc][3]) : "l"(h1.y), "l"(wd));
                    asm("fma.rn.f32x2 %0, %1, %2, %0;" : "+l"(acc[cc][4]) : "l"(h2.x), "l"(wd));
                    asm("fma.rn.f32x2 %0, %1, %2, %0;" : "+l"(acc[cc][5]) : "l"(h2.y), "l"(wd));
                    asm("fma.rn.f32x2 %0, %1, %2, %0;" : "+l"(acc[cc][6]) : "l"(h3.x), "l"(wd));
                    asm("fma.rn.f32x2 %0, %1, %2, %0;" : "+l"(acc[cc][7]) : "l"(h3.y), "l"(wd));
                }
                if (TWO_H) {
                    const float wv1 = wr[cc] * sh_a1[cc * FEAT + fb + kk];
                    unsigned long long wd1;
                    asm("mov.b64 %0, {%1, %1};" : "=l"(wd1) : "f"(wv1));
                    asm("fma.rn.f32x2 %0, %1, %2, %0;" : "+l"(acc[cc][0]) : "l"(g0.x), "l"(wd1));
                    asm("fma.rn.f32x2 %0, %1, %2, %0;" : "+l"(acc[cc][1]) : "l"(g0.y), "l"(wd1));
                    asm("fma.rn.f32x2 %0, %1, %2, %0;" : "+l"(acc[cc][2]) : "l"(g1.x), "l"(wd1));
                    asm("fma.rn.f32x2 %0, %1, %2, %0;" : "+l"(acc[cc][3]) : "l"(g1.y), "l"(wd1));
                    asm("fma.rn.f32x2 %0, %1, %2, %0;" : "+l"(acc[cc][4]) : "l"(g2.x), "l"(wd1));
                    asm("fma.rn.f32x2 %0, %1, %2, %0;" : "+l"(acc[cc][5]) : "l"(g2.y), "l"(wd1));
                    asm("fma.rn.f32x2 %0, %1, %2, %0;" : "+l"(acc[cc][6]) : "l"(g3.x), "l"(wd1));
                    asm("fma.rn.f32x2 %0, %1, %2, %0;" : "+l"(acc[cc][7]) : "l"(g3.y), "l"(wd1));
                }
            }
        }

        if (s + 1 < NST) store_h((s + 1) & 1);

        wb = (wb + 1 == 3) ? 0 : wb + 1;
        fb += 32; if (fb == FEAT) fb = 0;
    }

    // ---- cross-warp reduction (W ring reused), then atomics ----
    __syncthreads();
    unsigned long long* sred = reinterpret_cast<unsigned long long*>(dynsm);
#pragma unroll
    for (int cc = 0; cc < CPC; ++cc)
#pragma unroll
        for (int p = 0; p < 8; ++p)
            sred[w * 1024 + cc * 256 + p * 32 + lane] = acc[cc][p];
    __syncthreads();

#pragma unroll
    for (int r = 0; r < 8; ++r) {
        const int idx = tid + r * 128;     // (cc, p, m)
        const unsigned long long v0 = sred[idx];
        const unsigned long long v1 = sred[idx + 1024];
        const unsigned long long v2 = sred[idx + 2048];
        const unsigned long long v3 = sred[idx + 3072];
        unsigned long long s01, s23, sm;
        asm("add.rn.f32x2 %0, %1, %2;" : "=l"(s01) : "l"(v0), "l"(v1));
        asm("add.rn.f32x2 %0, %1, %2;" : "=l"(s23) : "l"(v2), "l"(v3));
        asm("add.rn.f32x2 %0, %1, %2;" : "=l"(sm)  : "l"(s01), "l"(s23));
        float lo, hi;
        asm("mov.b64 {%0, %1}, %2;" : "=f"(lo), "=f"(hi) : "l"(sm));
        const int cc = idx >> 8, p = (idx >> 5) & 7, m = idx & 31;
        float* yp = Y + ((size_t)(2 * p) * DIM + m) * FEAT + c0 + cc;
        atomicAdd(yp,                      lo);
        atomicAdd(yp + (size_t)DIM * FEAT, hi);
    }
}

// ---------------------------------------------------------------------------
// Plain transition matmul: Y[row, c] = sum_f H[row, f] * M[f, c]
// Grid = 512 rows -> fills the chip. Overwrites Y (initializes the layer
// accumulator); einsum atomicAdds on top.
// ---------------------------------------------------------------------------
__global__ void matmul_kernel(const float* __restrict__ H,
                              const float* __restrict__ M,
                              float* __restrict__ Y)
{
    __shared__ float sh[FEAT];
    const int row = blockIdx.x;
    const int t   = threadIdx.x;
    sh[t] = H[row * FEAT + t];
    __syncthreads();
    float s0 = 0.f, s1 = 0.f, s2 = 0.f, s3 = 0.f;
#pragma unroll 8
    for (int f = 0; f < FEAT; f += 4) {
        s0 = fmaf(sh[f    ], M[(f    ) * FEAT + t], s0);
        s1 = fmaf(sh[f + 1], M[(f + 1) * FEAT + t], s1);
        s2 = fmaf(sh[f + 2], M[(f + 2) * FEAT + t], s2);
        s3 = fmaf(sh[f + 3], M[(f + 3) * FEAT + t], s3);
    }
    Y[row * FEAT + t] = (s0 + s1) + (s2 + s3);
}

// ---------------------------------------------------------------------------
// LayerNorm over last two dims (6144 per n), eps=1e-5, no affine.
// (mean-over-terms division skipped: LN is scale-invariant)
// ---------------------------------------------------------------------------
__global__ void ln_kernel(const float* __restrict__ Y, float* __restrict__ O)
{
    const int n = blockIdx.x;
    const int t = threadIdx.x;
    const float* y = Y + (size_t)n * KTOT;

    float s = 0.f, q = 0.f;
    float vals[16];
#pragma unroll
    for (int r = 0; r < 16; ++r) {
        const float v = y[t + r * 384];
        vals[r] = v;
        s += v;
        q = fmaf(v, v, q);
    }
#pragma unroll
    for (int o = 16; o > 0; o >>= 1) {
        s += __shfl_xor_sync(0xffffffffu, s, o);
        q += __shfl_xor_sync(0xffffffffu, q, o);
    }
    __shared__ float ss[12], qs[12];
    __shared__ float mean_b, rstd_b;
    const int wid = t >> 5, ln = t & 31;
    if (ln == 0) { ss[wid] = s; qs[wid] = q; }
    __syncthreads();
    if (t == 0) {
        float S = 0.f, Q = 0.f;
#pragma unroll
        for (int i = 0; i < 12; ++i) { S += ss[i]; Q += qs[i]; }
        const float mean = S * (1.0f / KTOT);
        const float var  = Q * (1.0f / KTOT) - mean * mean;
        mean_b = mean;
        rstd_b = rsqrtf(var + 1e-5f);
    }
    __syncthreads();
    const float mean = mean_b, rstd = rstd_b;
#pragma unroll
    for (int r = 0; r < 16; ++r)
        O[(size_t)n * KTOT + t + r * 384] = (vals[r] - mean) * rstd;
}

// ---------------------------------------------------------------------------
extern "C" void kernel_launch(void* const* d_in, const int* in_sizes, int n_in,
                              void* d_out, int out_size)
{
    const float* x   = (const float*)d_in[0];
    const float* s2t = (const float*)d_in[1];
    const float* t2s = (const float*)d_in[2];
    const float* s0  = (const float*)d_in[3];
    const float* s1  = (const float*)d_in[4];
    // d_in[5] = s2 : unused by the 4-layer schedule
    const float* t0  = (const float*)d_in[6];
    const float* t1  = (const float*)d_in[7];
    const float* t2  = (const float*)d_in[8];
    float* out = (float*)d_out;

    float *ybuf, *h1, *h2;
    cudaGetSymbolAddress((void**)&ybuf, g_ybuf);
    cudaGetSymbolAddress((void**)&h1,   g_h1);
    cudaGetSymbolAddress((void**)&h2,   g_h2);

    const dim3 eg(KSPLIT, NCG);            // 12 x 48 = 576 CTAs
    const int  wsm = 3 * WBUFB;            // 48KB dynamic W ring

    // Opt-in for 48KB dynamic + static smem (host-side config, not a stream
    // op -> legal under graph capture). Idempotent, cheap.
    cudaFuncSetAttribute((const void*)einsum_kernel<false, 4>,
                         cudaFuncAttributeMaxDynamicSharedMemorySize, wsm);
    cudaFuncSetAttribute((const void*)einsum_kernel<true, 3>,
                         cudaFuncAttributeMaxDynamicSharedMemorySize, wsm);

    // Layer 1: y1 = einsum(x, s2t, t0) -> LN -> h1
    cudaMemsetAsync(ybuf, 0, YSZ * sizeof(float));
    einsum_kernel<false, 4><<<eg, 128, wsm>>>(s2t, x, t0, nullptr, nullptr, ybuf);
    ln_kernel<<<NN, 384>>>(ybuf, h1);

    // Layer 2: y2 = x@s1 + einsum(h1, t2s, s0) -> LN -> h2
    matmul_kernel<<<NN * DIM, FEAT>>>(x, s1, ybuf);
    einsum_kernel<false, 4><<<eg, 128, wsm>>>(t2s, h1, s0, nullptr, nullptr, ybuf);
    ln_kernel<<<NN, 384>>>(ybuf, h2);

    // Layer 3: y3 = h1@t1 + einsum(x, s2t, t2) + einsum(h2, s2t, t0)
    //          (both s2t einsums fused into ONE pass over W) -> LN -> out
    matmul_kernel<<<NN * DIM, FEAT>>>(h1, t1, ybuf);
    einsum_kernel<true, 3><<<eg, 128, wsm>>>(s2t, x, t2, h2, t0, ybuf);
    ln_kernel<<<NN, 384>>>(ybuf, out);
}

// round 14
// speedup vs baseline: 1.4543x; 1.0234x over previous
#include <cuda_runtime.h>
#include <cstddef>

// Problem constants
#define NN    16
#define DIM   32
#define FEAT  192
#define KTOT  (DIM*FEAT)      // 6144
#define YSZ   (NN*DIM*FEAT)   // 98304

// Einsum tiling
#define CPC    4               // c's per CTA (A folded into W scalar)
#define NCG    (FEAT/CPC)      // 48 c-groups
#define KSPLIT 12
#define KCTA   (KTOT/KSPLIT)   // 512
#define NST    (KCTA/32)       // 16 stages of 32 k's
#define KSTRIDE ((size_t)32 * FEAT * DIM)   // W float-stride of one 32-k stage
#define WBUFB  16384            // bytes per W ring buffer (32k*4c*32m*4B)

// Scratch (no allocations allowed -> device globals)
__device__ float g_ybuf[YSZ];
__device__ float g_h1[YSZ];
__device__ float g_h2[YSZ];

__device__ __forceinline__ void cp16(unsigned dst, const void* src) {
    asm volatile("cp.async.cg.shared.global [%0], [%1], 16;\n" :: "r"(dst), "l"(src));
}
#define CP_COMMIT() asm volatile("cp.async.commit_group;\n" ::: "memory")
#define CP_WAIT1()  asm volatile("cp.async.wait_group 1;\n" ::: "memory")

// ---------------------------------------------------------------------------
// Fused weighted einsum, ring-3 cp.async W pipeline, ONE barrier per stage:
//   Y[n, m, c] += sum_k H0[n,k] * A0[k%192, c] * W[k, c, m]   (+ H1/A1 stream)
// W viewed as [KTOT][FEAT][DIM]. Per 32-k stage the CTA stages the 16KB tile
// W[32k][4c][32m] via cp.async into a 3-deep ring (dynamic smem) and the 2KB
// h tile via a register pipeline one stage ahead.
// Thread mapping (R14): ci = lane>>3 (one c), m = (lane&7)*4 + j (4 m's).
// Per kk per thread: 1 LDS.128 (W, conflict-free) + 1 LDS.32 (A, 4-way
// broadcast) + 4 LDS.128 (h, broadcast) + 4 FMUL + 4 MOV + 32 fma.rn.f32x2.
// ---------------------------------------------------------------------------
template<bool TWO_H, int MINB>
__global__ void __launch_bounds__(128, MINB)
einsum_kernel(const float* __restrict__ W,
              const float* __restrict__ H0, const float* __restrict__ A0,
              const float* __restrict__ H1, const float* __restrict__ A1,
              float* __restrict__ Y)
{
    extern __shared__ __align__(16) float dynsm[];     // 3 * 4096 floats
    const int ks   = blockIdx.x;           // 0..KSPLIT-1
    const int c0   = blockIdx.y * CPC;     // 0..191 step 4
    const int tid  = threadIdx.x;
    const int w    = tid >> 5;
    const int lane = tid & 31;
    const int ci   = lane >> 3;            // this thread's c (0..3)
    const int mq   = lane & 7;             // m-quad: m = mq*4 + j

    __shared__ __align__(16) float2 shh [2][32][8];     // h stream0, 4KB
    __shared__ __align__(16) float2 shh2[TWO_H ? 2*32*8 : 8];
    __shared__ float sh_a0[FEAT * CPC];                 // f-major: [f][cc]
    __shared__ float sh_a1[TWO_H ? FEAT * CPC : 1];

    // Stage A columns for this CTA's 4 c's, f-major (visible after stage-0
    // barrier).
    for (int i = tid; i < CPC * FEAT; i += 128) {
        const int f = i >> 2, cc = i & 3;
        sh_a0[i] = A0[f * FEAT + c0 + cc];
        if (TWO_H) sh_a1[i] = A1[f * FEAT + c0 + cc];
    }

    const int kbase = ks * KCTA;
    const int kk_h  = tid >> 2;            // 0..31 : k-row this thread stages
    const int q     = tid & 3;             // n-quad

    // ---- running pointers ----
    const float* wsrc = W + ((size_t)(kbase + (tid >> 5)) * FEAT + c0) * DIM
                          + (tid & 31) * 4;
    const unsigned wdstb = (unsigned)__cvta_generic_to_shared(
        dynsm + (tid >> 5) * 128 + (tid & 31) * 4);
    const float* hsrc0 = H0 + kbase + kk_h;
    const float* hsrc1 = TWO_H ? (H1 + kbase + kk_h) : nullptr;

    auto copy_w = [&](unsigned dst, const float* src) {
#pragma unroll
        for (int j = 0; j < 8; ++j)
            cp16(dst + j * 4 * 512,
                 src + (size_t)j * 4 * FEAT * DIM);
    };

    float hv[4], hv2[4];
    auto load_h = [&](int soff) {
        const float* hp = hsrc0 + soff * 32;
#pragma unroll
        for (int j = 0; j < 4; ++j) hv[j] = hp[(4 * q + j) * KTOT];
        if (TWO_H) {
            const float* hq = hsrc1 + soff * 32;
#pragma unroll
            for (int j = 0; j < 4; ++j) hv2[j] = hq[(4 * q + j) * KTOT];
        }
    };
    auto store_h = [&](int buf) {
        *reinterpret_cast<float4*>(&shh[buf][kk_h][2 * q]) =
            make_float4(hv[0], hv[1], hv[2], hv[3]);
        if (TWO_H)
            *reinterpret_cast<float4*>(&shh2[(buf * 32 + kk_h) * 8 + 2 * q]) =
                make_float4(hv2[0], hv2[1], hv2[2], hv2[3]);
    };

    unsigned long long acc[4][8];          // [m-slot j][n-pair p]
#pragma unroll
    for (int j = 0; j < 4; ++j)
#pragma unroll
        for (int p = 0; p < 8; ++p) acc[j][p] = 0ull;

    // ---- pipeline prologue: copies for stages 0,1 in flight, h[0] staged ----
    copy_w(wdstb,         wsrc);            CP_COMMIT();
    copy_w(wdstb + WBUFB, wsrc + KSTRIDE);  CP_COMMIT();
    wsrc += 2 * KSTRIDE;                    // next copy target = stage 2
    load_h(0);
    store_h(0);

    const int kk0 = w * 8;
    int fb = kbase % FEAT;
    int wb = 0;                             // ring slot of stage s

    for (int s = 0; s < NST; ++s) {
        if (s + 1 < NST) load_h(s + 1);      // LDG issue, overlaps wait

        CP_WAIT1();                          // copy[s] complete (in-order)
        __syncthreads();                     // W[s]+h[s] visible; slot freed

        if (s + 2 < NST) {
            const int cb = (wb >= 1) ? wb - 1 : 2;   // (wb+2)%3
            copy_w(wdstb + cb * WBUFB, wsrc);
            wsrc += KSTRIDE;
        }
        CP_COMMIT();                         // (possibly empty) keeps counts

        const int   buf  = s & 1;
        const float* wcur = dynsm + wb * 4096;

#pragma unroll
        for (int i = 0; i < 8; ++i) {
            const int kk = kk0 + i;
            // One LDS.128: this thread's 4 W values W[kk][ci][mq*4..+3].
            const float4 wv4 = *reinterpret_cast<const float4*>(
                wcur + kk * 128 + ci * 32 + mq * 4);
            const float a0 = sh_a0[(fb + kk) * CPC + ci];
            const float wsc0 = wv4.x * a0, wsc1 = wv4.y * a0,
                        wsc2 = wv4.z * a0, wsc3 = wv4.w * a0;
            const float wsc[4] = {wsc0, wsc1, wsc2, wsc3};
            const ulonglong2* hr =
                reinterpret_cast<const ulonglong2*>(&shh[buf][kk][0]);
            const ulonglong2 h0 = hr[0], h1 = hr[1], h2 = hr[2], h3 = hr[3];
#pragma unroll
            for (int j = 0; j < 4; ++j) {
                unsigned long long wd;
                asm("mov.b64 %0, {%1, %1};" : "=l"(wd) : "f"(wsc[j]));
                asm("fma.rn.f32x2 %0, %1, %2, %0;" : "+l"(acc[j][0]) : "l"(h0.x), "l"(wd));
                asm("fma.rn.f32x2 %0, %1, %2, %0;" : "+l"(acc[j][1]) : "l"(h0.y), "l"(wd));
                asm("fma.rn.f32x2 %0, %1, %2, %0;" : "+l"(acc[j][2]) : "l"(h1.x), "l"(wd));
                asm("fma.rn.f32x2 %0, %1, %2, %0;" : "+l"(acc[j][3]) : "l"(h1.y), "l"(wd));
                asm("fma.rn.f32x2 %0, %1, %2, %0;" : "+l"(acc[j][4]) : "l"(h2.x), "l"(wd));
                asm("fma.rn.f32x2 %0, %1, %2, %0;" : "+l"(acc[j][5]) : "l"(h2.y), "l"(wd));
                asm("fma.rn.f32x2 %0, %1, %2, %0;" : "+l"(acc[j][6]) : "l"(h3.x), "l"(wd));
                asm("fma.rn.f32x2 %0, %1, %2, %0;" : "+l"(acc[j][7]) : "l"(h3.y), "l"(wd));
            }
            if (TWO_H) {
                const float a1 = sh_a1[(fb + kk) * CPC + ci];
                const float xsc0 = wv4.x * a1, xsc1 = wv4.y * a1,
                            xsc2 = wv4.z * a1, xsc3 = wv4.w * a1;
                const float xsc[4] = {xsc0, xsc1, xsc2, xsc3};
                const ulonglong2* gr = reinterpret_cast<const ulonglong2*>(
                    &shh2[(buf * 32 + kk) * 8]);
                const ulonglong2 g0 = gr[0], g1 = gr[1], g2 = gr[2], g3 = gr[3];
#pragma unroll
                for (int j = 0; j < 4; ++j) {
                    unsigned long long wd1;
                    asm("mov.b64 %0, {%1, %1};" : "=l"(wd1) : "f"(xsc[j]));
                    asm("fma.rn.f32x2 %0, %1, %2, %0;" : "+l"(acc[j][0]) : "l"(g0.x), "l"(wd1));
                    asm("fma.rn.f32x2 %0, %1, %2, %0;" : "+l"(acc[j][1]) : "l"(g0.y), "l"(wd1));
                    asm("fma.rn.f32x2 %0, %1, %2, %0;" : "+l"(acc[j][2]) : "l"(g1.x), "l"(wd1));
                    asm("fma.rn.f32x2 %0, %1, %2, %0;" : "+l"(acc[j][3]) : "l"(g1.y), "l"(wd1));
                    asm("fma.rn.f32x2 %0, %1, %2, %0;" : "+l"(acc[j][4]) : "l"(g2.x), "l"(wd1));
                    asm("fma.rn.f32x2 %0, %1, %2, %0;" : "+l"(acc[j][5]) : "l"(g2.y), "l"(wd1));
                    asm("fma.rn.f32x2 %0, %1, %2, %0;" : "+l"(acc[j][6]) : "l"(g3.x), "l"(wd1));
                    asm("fma.rn.f32x2 %0, %1, %2, %0;" : "+l"(acc[j][7]) : "l"(g3.y), "l"(wd1));
                }
            }
        }

        if (s + 1 < NST) store_h((s + 1) & 1);

        wb = (wb + 1 == 3) ? 0 : wb + 1;
        fb += 32; if (fb == FEAT) fb = 0;
    }

    // ---- cross-warp reduction (W ring reused), then atomics ----
    // Same sred layout as before: per warp-chunk, index = cc*256 + p*32 + m.
    __syncthreads();
    unsigned long long* sred = reinterpret_cast<unsigned long long*>(dynsm);
#pragma unroll
    for (int j = 0; j < 4; ++j)
#pragma unroll
        for (int p = 0; p < 8; ++p)
            sred[w * 1024 + ci * 256 + p * 32 + mq * 4 + j] = acc[j][p];
    __syncthreads();

#pragma unroll
    for (int r = 0; r < 8; ++r) {
        const int idx = tid + r * 128;     // (cc, p, m)
        const unsigned long long v0 = sred[idx];
        const unsigned long long v1 = sred[idx + 1024];
        const unsigned long long v2 = sred[idx + 2048];
        const unsigned long long v3 = sred[idx + 3072];
        unsigned long long s01, s23, sm;
        asm("add.rn.f32x2 %0, %1, %2;" : "=l"(s01) : "l"(v0), "l"(v1));
        asm("add.rn.f32x2 %0, %1, %2;" : "=l"(s23) : "l"(v2), "l"(v3));
        asm("add.rn.f32x2 %0, %1, %2;" : "=l"(sm)  : "l"(s01), "l"(s23));
        float lo, hi;
        asm("mov.b64 {%0, %1}, %2;" : "=f"(lo), "=f"(hi) : "l"(sm));
        const int cc = idx >> 8, p = (idx >> 5) & 7, m = idx & 31;
        float* yp = Y + ((size_t)(2 * p) * DIM + m) * FEAT + c0 + cc;
        atomicAdd(yp,                      lo);
        atomicAdd(yp + (size_t)DIM * FEAT, hi);
    }
}

// ---------------------------------------------------------------------------
// Plain transition matmul: Y[row, c] = sum_f H[row, f] * M[f, c]
// Grid = 512 rows -> fills the chip. Overwrites Y (initializes the layer
// accumulator); einsum atomicAdds on top.
// ---------------------------------------------------------------------------
__global__ void matmul_kernel(const float* __restrict__ H,
                              const float* __restrict__ M,
                              float* __restrict__ Y)
{
    __shared__ float sh[FEAT];
    const int row = blockIdx.x;
    const int t   = threadIdx.x;
    sh[t] = H[row * FEAT + t];
    __syncthreads();
    float s0 = 0.f, s1 = 0.f, s2 = 0.f, s3 = 0.f;
#pragma unroll 8
    for (int f = 0; f < FEAT; f += 4) {
        s0 = fmaf(sh[f    ], M[(f    ) * FEAT + t], s0);
        s1 = fmaf(sh[f + 1], M[(f + 1) * FEAT + t], s1);
        s2 = fmaf(sh[f + 2], M[(f + 2) * FEAT + t], s2);
        s3 = fmaf(sh[f + 3], M[(f + 3) * FEAT + t], s3);
    }
    Y[row * FEAT + t] = (s0 + s1) + (s2 + s3);
}

// ---------------------------------------------------------------------------
// LayerNorm over last two dims (6144 per n), eps=1e-5, no affine.
// (mean-over-terms division skipped: LN is scale-invariant)
// ---------------------------------------------------------------------------
__global__ void ln_kernel(const float* __restrict__ Y, float* __restrict__ O)
{
    const int n = blockIdx.x;
    const int t = threadIdx.x;
    const float* y = Y + (size_t)n * KTOT;

    float s = 0.f, q = 0.f;
    float vals[16];
#pragma unroll
    for (int r = 0; r < 16; ++r) {
        const float v = y[t + r * 384];
        vals[r] = v;
        s += v;
        q = fmaf(v, v, q);
    }
#pragma unroll
    for (int o = 16; o > 0; o >>= 1) {
        s += __shfl_xor_sync(0xffffffffu, s, o);
        q += __shfl_xor_sync(0xffffffffu, q, o);
    }
    __shared__ float ss[12], qs[12];
    __shared__ float mean_b, rstd_b;
    const int wid = t >> 5, ln = t & 31;
    if (ln == 0) { ss[wid] = s; qs[wid] = q; }
    __syncthreads();
    if (t == 0) {
        float S = 0.f, Q = 0.f;
#pragma unroll
        for (int i = 0; i < 12; ++i) { S += ss[i]; Q += qs[i]; }
        const float mean = S * (1.0f / KTOT);
        const float var  = Q * (1.0f / KTOT) - mean * mean;
        mean_b = mean;
        rstd_b = rsqrtf(var + 1e-5f);
    }
    __syncthreads();
    const float mean = mean_b, rstd = rstd_b;
#pragma unroll
    for (int r = 0; r < 16; ++r)
        O[(size_t)n * KTOT + t + r * 384] = (vals[r] - mean) * rstd;
}

// ---------------------------------------------------------------------------
extern "C" void kernel_launch(void* const* d_in, const int* in_sizes, int n_in,
                              void* d_out, int out_size)
{
    const float* x   = (const float*)d_in[0];
    const float* s2t = (const float*)d_in[1];
    const float* t2s = (const float*)d_in[2];
    const float* s0  = (const float*)d_in[3];
    const float* s1  = (const float*)d_in[4];
    // d_in[5] = s2 : unused by the 4-layer schedule
    const float* t0  = (const float*)d_in[6];
    const float* t1  = (const float*)d_in[7];
    const float* t2  = (const float*)d_in[8];
    float* out = (float*)d_out;

    float *ybuf, *h1, *h2;
    cudaGetSymbolAddress((void**)&ybuf, g_ybuf);
    cudaGetSymbolAddress((void**)&h1,   g_h1);
    cudaGetSymbolAddress((void**)&h2,   g_h2);

    const dim3 eg(KSPLIT, NCG);            // 12 x 48 = 576 CTAs
    const int  wsm = 3 * WBUFB;            // 48KB dynamic W ring

    // Opt-in for 48KB dynamic + static smem (host-side config, not a stream
    // op -> legal under graph capture). Idempotent, cheap.
    cudaFuncSetAttribute((const void*)einsum_kernel<false, 4>,
                         cudaFuncAttributeMaxDynamicSharedMemorySize, wsm);
    cudaFuncSetAttribute((const void*)einsum_kernel<true, 3>,
                         cudaFuncAttributeMaxDynamicSharedMemorySize, wsm);

    // Layer 1: y1 = einsum(x, s2t, t0) -> LN -> h1
    cudaMemsetAsync(ybuf, 0, YSZ * sizeof(float));
    einsum_kernel<false, 4><<<eg, 128, wsm>>>(s2t, x, t0, nullptr, nullptr, ybuf);
    ln_kernel<<<NN, 384>>>(ybuf, h1);

    // Layer 2: y2 = x@s1 + einsum(h1, t2s, s0) -> LN -> h2
    matmul_kernel<<<NN * DIM, FEAT>>>(x, s1, ybuf);
    einsum_kernel<false, 4><<<eg, 128, wsm>>>(t2s, h1, s0, nullptr, nullptr, ybuf);
    ln_kernel<<<NN, 384>>>(ybuf, h2);

    // Layer 3: y3 = h1@t1 + einsum(x, s2t, t2) + einsum(h2, s2t, t0)
    //          (both s2t einsums fused into ONE pass over W) -> LN -> out
    matmul_kernel<<<NN * DIM, FEAT>>>(h1, t1, ybuf);
    einsum_kernel<true, 3><<<eg, 128, wsm>>>(s2t, x, t2, h2, t0, ybuf);
    ln_kernel<<<NN, 384>>>(ybuf, out);
}